// round 1
// baseline (speedup 1.0000x reference)
#include <cuda_runtime.h>

#define B_TOTAL 4096
#define T_STEPS 256
#define IN_DIM 16
#define H1 64
#define G1 256           // 4*H1
#define BPB 2            // batches per block
#define NTHREADS 288     // 8 gate warps + 1 layer2 warp

using u64 = unsigned long long;

__device__ __forceinline__ u64 pack2(float x, float y) {
    u64 r; asm("mov.b64 %0, {%1, %2};" : "=l"(r) : "f"(x), "f"(y)); return r;
}
__device__ __forceinline__ void unpack2(u64 v, float &x, float &y) {
    asm("mov.b64 {%0, %1}, %2;" : "=f"(x), "=f"(y) : "l"(v));
}
__device__ __forceinline__ u64 ffma2(u64 a, u64 b, u64 c) {
    u64 d; asm("fma.rn.f32x2 %0, %1, %2, %3;" : "=l"(d) : "l"(a), "l"(b), "l"(c)); return d;
}
__device__ __forceinline__ float ex2f(float x){ float y; asm("ex2.approx.f32 %0, %1;" : "=f"(y) : "f"(x)); return y; }
__device__ __forceinline__ float rcpf(float x){ float y; asm("rcp.approx.f32 %0, %1;" : "=f"(y) : "f"(x)); return y; }
// sigmoid(x) = 1/(1+2^(-x*log2e)),  tanh(x) = 2/(1+2^(-2x*log2e)) - 1
__device__ __forceinline__ float sigmoid_f(float x){ return rcpf(1.0f + ex2f(-1.4426950408889634f * x)); }
__device__ __forceinline__ float tanh_f(float x){ return 2.0f * rcpf(1.0f + ex2f(-2.8853900817779268f * x)) - 1.0f; }

__global__ void __launch_bounds__(NTHREADS)
lstm2_fused_kernel(
    const float* __restrict__ x,
    const float* __restrict__ w_ih1, const float* __restrict__ w_hh1,
    const float* __restrict__ b_ih1, const float* __restrict__ b_hh1,
    const float* __restrict__ w_ih2, const float* __restrict__ w_hh2,
    const float* __restrict__ b_ih2, const float* __restrict__ b_hh2,
    const float* __restrict__ fc_w,  const float* __restrict__ fc_b,
    float* __restrict__ out)
{
    __shared__ float xs[BPB][T_STEPS][IN_DIM];    // 32 KB: whole input window for this block
    __shared__ float h1buf[2][BPB][H1];           // double-buffered layer1 hidden
    __shared__ float gates_s[BPB][G1];            // activated gates
    __shared__ float l2c[12];                     // layer2 consts: bias2[4], whh2[4], fcw, fcb

    const int tid = threadIdx.x;
    const int b0  = blockIdx.x * BPB;

    // ---- prologue: stage x into smem (coalesced float4) ----
    {
        const int per_b = T_STEPS * IN_DIM / 4;   // 1024 float4 per batch
        float4* xsd = (float4*)&xs[0][0][0];
        for (int i = tid; i < BPB * per_b; i += NTHREADS) {
            int bb = i / per_b;
            int r  = i - bb * per_b;
            xsd[i] = ((const float4*)(x + (size_t)(b0 + bb) * T_STEPS * IN_DIM))[r];
        }
    }
    if (tid < BPB * H1) h1buf[0][tid >> 6][tid & 63] = 0.0f;
    if (tid == 0) {
        #pragma unroll
        for (int g = 0; g < 4; ++g) {
            l2c[g]     = b_ih2[g] + b_hh2[g];
            l2c[4 + g] = w_hh2[g];
        }
        l2c[8] = fc_w[0];
        l2c[9] = fc_b[0];
    }

    // ---- per-thread register state ----
    // gate threads (tid < 256): weight rows as f32x2 pairs
    u64 wih[IN_DIM / 2];
    u64 whh[H1 / 2];
    float bias = 0.0f;
    float c_state = 0.0f;           // c1 for (bb,j) on tid<128

    if (tid < G1) {
        const ulonglong2* wi = (const ulonglong2*)(w_ih1 + tid * IN_DIM);
        #pragma unroll
        for (int k = 0; k < IN_DIM / 4; ++k) { ulonglong2 v = wi[k]; wih[2*k] = v.x; wih[2*k+1] = v.y; }
        const ulonglong2* wh = (const ulonglong2*)(w_hh1 + tid * H1);
        #pragma unroll
        for (int k = 0; k < H1 / 4; ++k) { ulonglong2 v = wh[k]; whh[2*k] = v.x; whh[2*k+1] = v.y; }
        bias = b_ih1[tid] + b_hh1[tid];
    }

    // layer2 warp (tid >= 256): lane l -> gate gg = l>>3, slice pp = l&7 (8 weights each)
    const int lane = tid - G1;
    const int gg = (lane >= 0) ? (lane >> 3) : 0;
    const int pp = (lane >= 0) ? (lane & 7) : 0;
    float w2[8];
    float h2s[BPB], c2s[BPB];
    #pragma unroll
    for (int bb = 0; bb < BPB; ++bb) { h2s[bb] = 0.0f; c2s[bb] = 0.0f; }
    if (tid >= G1) {
        #pragma unroll
        for (int e = 0; e < 8; ++e) w2[e] = w_ih2[gg * H1 + pp * 8 + e];
    } else {
        #pragma unroll
        for (int e = 0; e < 8; ++e) w2[e] = 0.0f;
    }

    // layer2 + FC for timestep tt, reading h1 from h1buf[curbuf]
    auto layer2_step = [&](int tt, int curbuf) {
        #pragma unroll
        for (int bb = 0; bb < BPB; ++bb) {
            const float* hr = &h1buf[curbuf][bb][0];
            float p = 0.0f;
            #pragma unroll
            for (int e = 0; e < 8; ++e) p = fmaf(w2[e], hr[pp * 8 + e], p);
            // reduce within 8-lane groups
            p += __shfl_xor_sync(0xffffffffu, p, 1);
            p += __shfl_xor_sync(0xffffffffu, p, 2);
            p += __shfl_xor_sync(0xffffffffu, p, 4);
            float s0 = __shfl_sync(0xffffffffu, p, 0);
            float s1 = __shfl_sync(0xffffffffu, p, 8);
            float s2 = __shfl_sync(0xffffffffu, p, 16);
            float s3 = __shfl_sync(0xffffffffu, p, 24);
            if (lane == 0) {
                float hp = h2s[bb];
                float i2 = sigmoid_f(s0 + l2c[0] + l2c[4] * hp);
                float f2 = sigmoid_f(s1 + l2c[1] + l2c[5] * hp);
                float g2 = tanh_f  (s2 + l2c[2] + l2c[6] * hp);
                float o2 = sigmoid_f(s3 + l2c[3] + l2c[7] * hp);
                float c2 = fmaf(f2, c2s[bb], i2 * g2);
                c2s[bb] = c2;
                float h2 = o2 * tanh_f(c2);
                h2s[bb] = h2;
                out[(size_t)(b0 + bb) * T_STEPS + tt] = fmaf(h2, l2c[8], l2c[9]);
            }
        }
    };

    // ---- main recurrence ----
    int cur = 0;
    for (int t = 0; t < T_STEPS; ++t) {
        __syncthreads();   // h1buf[cur] ready; gates_s free
        if (tid < G1) {
            const ulonglong2* x0 = (const ulonglong2*)&xs[0][t][0];
            const ulonglong2* x1 = (const ulonglong2*)&xs[1][t][0];
            u64 a0 = pack2(bias, 0.0f);
            u64 a1 = pack2(bias, 0.0f);
            #pragma unroll
            for (int k = 0; k < IN_DIM / 4; ++k) {
                ulonglong2 v0 = x0[k], v1 = x1[k];
                a0 = ffma2(wih[2*k],   v0.x, a0);  a1 = ffma2(wih[2*k],   v1.x, a1);
                a0 = ffma2(wih[2*k+1], v0.y, a0);  a1 = ffma2(wih[2*k+1], v1.y, a1);
            }
            const ulonglong2* h0p = (const ulonglong2*)&h1buf[cur][0][0];
            const ulonglong2* h1p = (const ulonglong2*)&h1buf[cur][1][0];
            #pragma unroll
            for (int k = 0; k < H1 / 4; ++k) {
                ulonglong2 v0 = h0p[k], v1 = h1p[k];
                a0 = ffma2(whh[2*k],   v0.x, a0);  a1 = ffma2(whh[2*k],   v1.x, a1);
                a0 = ffma2(whh[2*k+1], v0.y, a0);  a1 = ffma2(whh[2*k+1], v1.y, a1);
            }
            float g0x, g0y, g1x, g1y;
            unpack2(a0, g0x, g0y);
            unpack2(a1, g1x, g1y);
            float ga = g0x + g0y;
            float gb = g1x + g1y;
            int wtype = tid >> 6;           // 0:i 1:f 2:g 3:o  (uniform per warp)
            if (wtype == 2) { ga = tanh_f(ga);    gb = tanh_f(gb); }
            else            { ga = sigmoid_f(ga); gb = sigmoid_f(gb); }
            gates_s[0][tid] = ga;
            gates_s[1][tid] = gb;
        } else {
            if (t > 0) layer2_step(t - 1, cur);   // pipelined one step behind
        }
        __syncthreads();   // gates ready
        if (tid < BPB * H1) {
            int bb = tid >> 6, j = tid & 63;
            float gi = gates_s[bb][j];
            float gf = gates_s[bb][H1 + j];
            float gc = gates_s[bb][2 * H1 + j];
            float go = gates_s[bb][3 * H1 + j];
            c_state = fmaf(gf, c_state, gi * gc);
            h1buf[cur ^ 1][bb][j] = go * tanh_f(c_state);
        }
        cur ^= 1;
    }
    __syncthreads();
    if (tid >= G1) layer2_step(T_STEPS - 1, cur);   // drain: last timestep of layer2
}

extern "C" void kernel_launch(void* const* d_in, const int* in_sizes, int n_in,
                              void* d_out, int out_size) {
    (void)in_sizes; (void)n_in; (void)out_size;
    lstm2_fused_kernel<<<B_TOTAL / BPB, NTHREADS>>>(
        (const float*)d_in[0],
        (const float*)d_in[1], (const float*)d_in[2],
        (const float*)d_in[3], (const float*)d_in[4],
        (const float*)d_in[5], (const float*)d_in[6],
        (const float*)d_in[7], (const float*)d_in[8],
        (const float*)d_in[9], (const float*)d_in[10],
        (float*)d_out);
}